// round 10
// baseline (speedup 1.0000x reference)
#include <cuda_runtime.h>
#include <math.h>

#define B      256
#define NNEG   1000
#define H      3
#define D      128
#define NMIN   250
#define EPSF   1e-6f
#define BT     2                 // samples per block
#define NBLK   (B / BT)          // 128 blocks
#define NTHR   512               // 16 warps
#define ROUNDS 6                 // 96 chunks = 16 warps * 6 rounds; 8 c-slots/chunk

__device__ float        g_partial[NBLK];
__device__ unsigned int g_ticket = 0;

// ---- packed f32x2 FMA (sm_103a FFMA2; operands pre-packed by 128-bit loads) ----
__device__ __forceinline__ void ffma2(unsigned long long& d,
                                      unsigned long long a,
                                      unsigned long long b) {
    asm("fma.rn.f32x2 %0, %1, %2, %0;" : "+l"(d) : "l"(a), "l"(b));
}
__device__ __forceinline__ float upsum(unsigned long long v) {
    return __uint_as_float((unsigned)v) + __uint_as_float((unsigned)(v >> 32));
}
__device__ __forceinline__ float group_sum8(float v) {
    v += __shfl_xor_sync(0xffffffffu, v, 1);
    v += __shfl_xor_sync(0xffffffffu, v, 2);
    v += __shfl_xor_sync(0xffffffffu, v, 4);
    return v;
}
__device__ __forceinline__ float warp_sum32(float v) {
#pragma unroll
    for (int o = 16; o > 0; o >>= 1) v += __shfl_xor_sync(0xffffffffu, v, o);
    return v;
}
__device__ __forceinline__ unsigned smem_u32(const void* p) {
    unsigned a;
    asm("{ .reg .u64 t; cvta.to.shared.u64 t, %1; cvt.u32.u64 %0, t; }"
        : "=r"(a) : "l"(p));
    return a;
}

struct Task { int h, cA, cB, idA, idB; bool vA, pA, vB, pB; };

__device__ __forceinline__ Task mktask(int chunkid, int g, const int* pl) {
    Task t;
    t.h = chunkid >> 5;                 // 0..2, warp-uniform
    int cbase = (chunkid & 31) * 8;
    t.cA = cbase + 2 * g; t.cB = t.cA + 1;
    t.vA = t.cA < NMIN + BT;
    t.pA = t.vA && (t.cA >= NMIN);
    t.idA = t.pA ? pl[(t.cA - NMIN) * H + t.h] : (t.vA ? t.cA : 0);
    t.vB = t.cB < NMIN + BT;
    t.pB = t.vB && (t.cB >= NMIN);
    t.idB = t.pB ? pl[(t.cB - NMIN) * H + t.h] : (t.vB ? t.cB : 0);
    return t;
}

__global__ __launch_bounds__(NTHR, 1)
void hirl_fused(const float* __restrict__ se,
                const float* __restrict__ c0,
                const float* __restrict__ c1,
                const float* __restrict__ c2,
                const int* __restrict__ i2c0,
                const int* __restrict__ i2c1,
                const int* __restrict__ i2c2,
                const int* __restrict__ idx,
                const int* __restrict__ negid,
                float* __restrict__ out)
{
    __shared__ float4 s_se4[BT * H * 32];     // 6 normalized rows x 128 floats
    __shared__ float  s_sims[BT * H * NMIN];  // [s][h][c]
    __shared__ int    s_neg[BT * NNEG * H];   // this block's negative ids (24 KB)
    __shared__ int    s_poslab[BT * H];
    __shared__ float  s_psim[BT * H];
    __shared__ float  s_red[16][2];
    __shared__ float  s_tot[BT];
    __shared__ bool   s_amLast;

    const int tid  = threadIdx.x;
    const int warp = tid >> 5;
    const int lane = tid & 31;
    const int b0   = blockIdx.x * BT;

    // ====== Kick off async copy of this block's negid slice (24 KB, LDGSTS) ======
    {
        unsigned sdst = smem_u32(s_neg);
        const int4* gsrc = (const int4*)(negid + (long)b0 * NNEG * H);
#pragma unroll
        for (int k = 0; k < 3; k++) {
            int i = tid + k * NTHR;
            if (i < (BT * NNEG * H) / 4)
                asm volatile("cp.async.ca.shared.global [%0], [%1], 16;"
                             :: "r"(sdst + i * 16), "l"(gsrc + i));
        }
        asm volatile("cp.async.commit_group;" ::: "memory");
    }

    // ================= Phase A: normalize se rows + positive labels =================
    if (warp < BT * H) {
        int s = warp / H, h = warp - s * H;
        float4 v = ((const float4*)(se + ((long)(b0 + s) * H + h) * D))[lane];
        float ss = warp_sum32(v.x * v.x + v.y * v.y + v.z * v.z + v.w * v.w);
        float inv = rsqrtf(fmaxf(ss, 1e-24f));
        v.x *= inv; v.y *= inv; v.z *= inv; v.w *= inv;
        s_se4[(s * H + h) * 32 + lane] = v;
    } else if (warp == 6 && lane < BT * H) {
        int s = lane / H, h = lane - s * H;
        const int* p = (h == 0) ? i2c0 : ((h == 1) ? i2c1 : i2c2);
        s_poslab[lane] = p[idx[b0 + s]];
    }
    __syncthreads();

    // ================= Phase B: half-sim table + positive sims =================
    // Same geometry as before (6 rounds x 2 tasks/group, ghost slots = pos dots),
    // plus prefetch.global.L1 of round r+1's centroid rows during round r.
    {
        const int g   = lane >> 3;
        const int sub = lane & 7;
        const float* cptr[H] = { c0, c1, c2 };

        ulonglong2 seR[BT][4];     // se rows of current h, 16 floats/lane
        int hcur = -1;

#pragma unroll 1
        for (int r = 0; r < ROUNDS; r++) {
            Task t = mktask(r * 16 + warp, g, s_poslab);

            // prefetch next round's rows into L1 (no registers, no scoreboard)
            if (r + 1 < ROUNDS) {
                Task tn = mktask((r + 1) * 16 + warp, g, s_poslab);
                const char* pA = (const char*)(cptr[tn.h] + (long)tn.idA * D) + sub * 64;
                const char* pB = (const char*)(cptr[tn.h] + (long)tn.idB * D) + sub * 64;
                asm volatile("prefetch.global.L1 [%0]; prefetch.global.L1 [%1];"
                             :: "l"(pA), "l"(pB));
            }

            if (t.h != hcur) {
                hcur = t.h;
#pragma unroll
                for (int s2 = 0; s2 < BT; s2++)
#pragma unroll
                    for (int j = 0; j < 4; j++)
                        seR[s2][j] = ((const ulonglong2*)
                            &s_se4[(s2 * H + hcur) * 32])[j * 8 + sub];
            }

            const ulonglong2* cpA = (const ulonglong2*)(cptr[t.h] + (long)t.idA * D);
            const ulonglong2* cpB = (const ulonglong2*)(cptr[t.h] + (long)t.idB * D);
            ulonglong2 cvA[4], cvB[4];
#pragma unroll
            for (int j = 0; j < 4; j++) { cvA[j] = cpA[j * 8 + sub];
                                          cvB[j] = cpB[j * 8 + sub]; }

            unsigned long long ssA = 0, d0A = 0, d1A = 0;
            unsigned long long ssB = 0, d0B = 0, d1B = 0;
#pragma unroll
            for (int j = 0; j < 4; j++) {
                ffma2(ssA, cvA[j].x, cvA[j].x); ffma2(ssA, cvA[j].y, cvA[j].y);
                ffma2(d0A, seR[0][j].x, cvA[j].x); ffma2(d0A, seR[0][j].y, cvA[j].y);
                ffma2(d1A, seR[1][j].x, cvA[j].x); ffma2(d1A, seR[1][j].y, cvA[j].y);
                ffma2(ssB, cvB[j].x, cvB[j].x); ffma2(ssB, cvB[j].y, cvB[j].y);
                ffma2(d0B, seR[0][j].x, cvB[j].x); ffma2(d0B, seR[0][j].y, cvB[j].y);
                ffma2(d1B, seR[1][j].x, cvB[j].x); ffma2(d1B, seR[1][j].y, cvB[j].y);
            }
            // 6 independent 3-shfl reduction chains
            float sfA = group_sum8(upsum(ssA));
            float f0A = group_sum8(upsum(d0A));
            float f1A = group_sum8(upsum(d1A));
            float sfB = group_sum8(upsum(ssB));
            float f0B = group_sum8(upsum(d0B));
            float f1B = group_sum8(upsum(d1B));
            float invA = 0.5f * rsqrtf(fmaxf(sfA, 1e-24f));
            float invB = 0.5f * rsqrtf(fmaxf(sfB, 1e-24f));

            if (sub == 0) {
                if (t.vA) {
                    if (!t.pA) {
                        s_sims[(0 * H + t.h) * NMIN + t.cA] = __fmaf_rn(f0A, invA, 0.5f);
                        s_sims[(1 * H + t.h) * NMIN + t.cA] = __fmaf_rn(f1A, invA, 0.5f);
                    } else {
                        int s2 = t.cA - NMIN;
                        s_psim[s2 * H + t.h] =
                            __fmaf_rn((s2 == 0) ? f0A : f1A, invA, 0.5f);
                    }
                }
                if (t.vB) {
                    if (!t.pB) {
                        s_sims[(0 * H + t.h) * NMIN + t.cB] = __fmaf_rn(f0B, invB, 0.5f);
                        s_sims[(1 * H + t.h) * NMIN + t.cB] = __fmaf_rn(f1B, invB, 0.5f);
                    } else {
                        int s2 = t.cB - NMIN;
                        s_psim[s2 * H + t.h] =
                            __fmaf_rn((s2 == 0) ? f0B : f1B, invB, 0.5f);
                    }
                }
            }
        }
    }
    asm volatile("cp.async.wait_all;" ::: "memory");   // negid slice resident
    __syncthreads();

    // ================= Phase C: negative losses (all-smem) =================
    {
        const int s  = tid >> 8;          // sample 0..1
        const int lg = tid & 255;
        const float* simrow = &s_sims[s * H * NMIN];
        const int pl0 = s_poslab[s * H + 0];
        const int pl1 = s_poslab[s * H + 1];
        const int pl2 = s_poslab[s * H + 2];

        float sum = 0.f, cnt = 0.f;
#pragma unroll
        for (int it = 0; it < 4; it++) {
            int n = lg + it * 256;
            if (n < NNEG) {
                const int* q = s_neg + (s * NNEG + n) * H;
                int i0 = q[0], i1 = q[1], i2 = q[2];
                // ids are < NMIN by the reference's construction; clamp is defensive
                float p0 = simrow[0 * NMIN + ((i0 < NMIN) ? i0 : NMIN - 1)];
                float p1 = simrow[1 * NMIN + ((i1 < NMIN) ? i1 : NMIN - 1)];
                float p2 = simrow[2 * NMIN + ((i2 < NMIN) ? i2 : NMIN - 1)];
                float p = p0 * p1 * p2;
                if ((i0 != pl0) | (i1 != pl1) | (i2 != pl2)) {
                    sum += -__logf(1.0f - p + EPSF);
                    cnt += 1.0f;
                }
            }
        }
        sum = warp_sum32(sum);
        cnt = warp_sum32(cnt);
        if (lane == 0) { s_red[warp][0] = sum; s_red[warp][1] = cnt; }
    }
    __syncthreads();

    if (tid < BT) {
        int s = tid;
        float sum = 0.f, cnt = 0.f;
#pragma unroll
        for (int w = 0; w < 8; w++) { sum += s_red[s * 8 + w][0]; cnt += s_red[s * 8 + w][1]; }
        float pprod = s_psim[s * H + 0] * s_psim[s * H + 1] * s_psim[s * H + 2];
        s_tot[s] = -__logf(pprod + EPSF) + sum / (cnt + EPSF);
    }
    __syncthreads();
    if (tid == 0)
        g_partial[blockIdx.x] = s_tot[0] + s_tot[1];

    // ================= Final: last block reduces 128 partials =================
    if (tid == 0) {
        __threadfence();
        s_amLast = (atomicAdd(&g_ticket, 1u) == NBLK - 1);
    }
    __syncthreads();
    if (s_amLast && warp == 0) {
        volatile float* gp = g_partial;
        float v = gp[lane] + gp[lane + 32] + gp[lane + 64] + gp[lane + 96];
        v = warp_sum32(v);
        if (lane == 0) {
            out[0] = v * (1.0f / (2.0f * (float)B));
            g_ticket = 0;
        }
    }
}

extern "C" void kernel_launch(void* const* d_in, const int* in_sizes, int n_in,
                              void* d_out, int out_size)
{
    const float* se   = (const float*)d_in[0];
    const float* c0   = (const float*)d_in[1];
    const float* c1   = (const float*)d_in[2];
    const float* c2   = (const float*)d_in[3];
    const int*   i2c0 = (const int*)d_in[4];
    const int*   i2c1 = (const int*)d_in[5];
    const int*   i2c2 = (const int*)d_in[6];
    const int*   idx  = (const int*)d_in[7];
    const int*   neg  = (const int*)d_in[8];
    float*       out  = (float*)d_out;

    hirl_fused<<<NBLK, NTHR>>>(se, c0, c1, c2, i2c0, i2c1, i2c2, idx, neg, out);
}

// round 11
// speedup vs baseline: 1.1805x; 1.1805x over previous
#include <cuda_runtime.h>
#include <math.h>

#define B      256
#define NNEG   1000
#define H      3
#define D      128
#define NMIN   250
#define EPSF   1e-6f
#define BT     2                 // samples per block
#define NBLK   (B / BT)          // 128 blocks
#define NTHR   512               // 16 warps

__device__ float        g_partial[NBLK];
__device__ unsigned int g_ticket = 0;

// ---- packed f32x2 FMA (sm_103a FFMA2; operands pre-packed by 128-bit loads) ----
__device__ __forceinline__ void ffma2(unsigned long long& d,
                                      unsigned long long a,
                                      unsigned long long b) {
    asm("fma.rn.f32x2 %0, %1, %2, %0;" : "+l"(d) : "l"(a), "l"(b));
}
__device__ __forceinline__ float upsum(unsigned long long v) {
    return __uint_as_float((unsigned)v) + __uint_as_float((unsigned)(v >> 32));
}
__device__ __forceinline__ float group_sum8(float v) {
    v += __shfl_xor_sync(0xffffffffu, v, 1);
    v += __shfl_xor_sync(0xffffffffu, v, 2);
    v += __shfl_xor_sync(0xffffffffu, v, 4);
    return v;
}
__device__ __forceinline__ float warp_sum32(float v) {
#pragma unroll
    for (int o = 16; o > 0; o >>= 1) v += __shfl_xor_sync(0xffffffffu, v, o);
    return v;
}

__global__ __launch_bounds__(NTHR, 1)
void hirl_fused(const float* __restrict__ se,
                const float* __restrict__ c0,
                const float* __restrict__ c1,
                const float* __restrict__ c2,
                const int* __restrict__ i2c0,
                const int* __restrict__ i2c1,
                const int* __restrict__ i2c2,
                const int* __restrict__ idx,
                const int* __restrict__ negid,
                float* __restrict__ out)
{
    __shared__ float4 s_se4[BT * H * 32];     // 6 normalized rows x 128 floats
    __shared__ float  s_sims[BT * H * NMIN];  // [s][h][c]
    __shared__ int    s_poslab[BT * H];
    __shared__ float  s_psim[BT * H];
    __shared__ float  s_red[16][2];
    __shared__ float  s_tot[BT];
    __shared__ bool   s_amLast;

    const int tid  = threadIdx.x;
    const int warp = tid >> 5;
    const int lane = tid & 31;
    const int b0   = blockIdx.x * BT;

    // ================= Phase A: normalize se rows + positive labels =================
    if (warp < BT * H) {
        int s = warp / H, h = warp - s * H;
        float4 v = ((const float4*)(se + ((long)(b0 + s) * H + h) * D))[lane];
        float ss = warp_sum32(v.x * v.x + v.y * v.y + v.z * v.z + v.w * v.w);
        float inv = rsqrtf(fmaxf(ss, 1e-24f));
        v.x *= inv; v.y *= inv; v.z *= inv; v.w *= inv;
        s_se4[(s * H + h) * 32 + lane] = v;
    } else if (warp == 6 && lane < BT * H) {
        int s = lane / H, h = lane - s * H;
        const int* p = (h == 0) ? i2c0 : ((h == 1) ? i2c1 : i2c2);
        s_poslab[lane] = p[idx[b0 + s]];
    }
    __syncthreads();

    // ================= Phase B: half-sim table + positive sims =================
    // 3 compile-time h-phases x 2 subrounds. Per subround, 8-lane group g
    // handles c = subr*128 + warp*8 + 2g and +1 (2 tasks -> 6 independent FFMA
    // chains + 6 independent 3-SHFL reductions). Ghost slots c==250/251 carry
    // the positive-path dots for s=0/1; c>=252 idle. Full unroll lets ptxas
    // hoist subround-1 loads above subround-0's reduction tail.
    {
        const int g   = lane >> 3;
        const int sub = lane & 7;

#pragma unroll
        for (int h = 0; h < H; h++) {
            const float* cents = (h == 0) ? c0 : ((h == 1) ? c1 : c2);

            ulonglong2 seR[BT][4];     // se rows of hierarchy h, 16 floats/lane
#pragma unroll
            for (int s2 = 0; s2 < BT; s2++)
#pragma unroll
                for (int j = 0; j < 4; j++)
                    seR[s2][j] = ((const ulonglong2*)
                        &s_se4[(s2 * H + h) * 32])[j * 8 + sub];

#pragma unroll
            for (int subr = 0; subr < 2; subr++) {
                const int cA = subr * 128 + warp * 8 + 2 * g;
                const int cB = cA + 1;
                const bool vA = cA < NMIN + BT, pA = vA && (cA >= NMIN);
                const bool vB = cB < NMIN + BT, pB = vB && (cB >= NMIN);
                const int idA = pA ? s_poslab[(cA - NMIN) * H + h] : (vA ? cA : 0);
                const int idB = pB ? s_poslab[(cB - NMIN) * H + h] : (vB ? cB : 0);

                const ulonglong2* cpA = (const ulonglong2*)(cents + (long)idA * D);
                const ulonglong2* cpB = (const ulonglong2*)(cents + (long)idB * D);
                ulonglong2 cvA[4], cvB[4];
#pragma unroll
                for (int j = 0; j < 4; j++) { cvA[j] = cpA[j * 8 + sub];
                                              cvB[j] = cpB[j * 8 + sub]; }

                unsigned long long ssA = 0, d0A = 0, d1A = 0;
                unsigned long long ssB = 0, d0B = 0, d1B = 0;
#pragma unroll
                for (int j = 0; j < 4; j++) {
                    ffma2(ssA, cvA[j].x, cvA[j].x); ffma2(ssA, cvA[j].y, cvA[j].y);
                    ffma2(d0A, seR[0][j].x, cvA[j].x); ffma2(d0A, seR[0][j].y, cvA[j].y);
                    ffma2(d1A, seR[1][j].x, cvA[j].x); ffma2(d1A, seR[1][j].y, cvA[j].y);
                    ffma2(ssB, cvB[j].x, cvB[j].x); ffma2(ssB, cvB[j].y, cvB[j].y);
                    ffma2(d0B, seR[0][j].x, cvB[j].x); ffma2(d0B, seR[0][j].y, cvB[j].y);
                    ffma2(d1B, seR[1][j].x, cvB[j].x); ffma2(d1B, seR[1][j].y, cvB[j].y);
                }
                // 6 independent 3-shfl reduction chains
                float sfA = group_sum8(upsum(ssA));
                float f0A = group_sum8(upsum(d0A));
                float f1A = group_sum8(upsum(d1A));
                float sfB = group_sum8(upsum(ssB));
                float f0B = group_sum8(upsum(d0B));
                float f1B = group_sum8(upsum(d1B));
                float invA = 0.5f * rsqrtf(fmaxf(sfA, 1e-24f));
                float invB = 0.5f * rsqrtf(fmaxf(sfB, 1e-24f));

                if (sub == 0) {
                    if (vA) {
                        if (!pA) {
                            s_sims[(0 * H + h) * NMIN + cA] = __fmaf_rn(f0A, invA, 0.5f);
                            s_sims[(1 * H + h) * NMIN + cA] = __fmaf_rn(f1A, invA, 0.5f);
                        } else {
                            int s2 = cA - NMIN;
                            s_psim[s2 * H + h] =
                                __fmaf_rn((s2 == 0) ? f0A : f1A, invA, 0.5f);
                        }
                    }
                    if (vB) {
                        if (!pB) {
                            s_sims[(0 * H + h) * NMIN + cB] = __fmaf_rn(f0B, invB, 0.5f);
                            s_sims[(1 * H + h) * NMIN + cB] = __fmaf_rn(f1B, invB, 0.5f);
                        } else {
                            int s2 = cB - NMIN;
                            s_psim[s2 * H + h] =
                                __fmaf_rn((s2 == 0) ? f0B : f1B, invB, 0.5f);
                        }
                    }
                }
            }
        }
    }
    __syncthreads();

    // ================= Phase C: negative losses =================
    {
        const int s  = tid >> 8;          // sample 0..1
        const int lg = tid & 255;
        const int b  = b0 + s;
        const float* simrow = &s_sims[s * H * NMIN];
        const int pl0 = s_poslab[s * H + 0];
        const int pl1 = s_poslab[s * H + 1];
        const int pl2 = s_poslab[s * H + 2];

        float sum = 0.f, cnt = 0.f;
#pragma unroll
        for (int it = 0; it < 4; it++) {
            int n = lg + it * 256;
            if (n < NNEG) {
                const int* q = negid + ((long)b * NNEG + n) * H;
                int i0 = q[0], i1 = q[1], i2 = q[2];
                // ids are < NMIN by the reference's construction; clamp is defensive
                float p0 = simrow[0 * NMIN + ((i0 < NMIN) ? i0 : NMIN - 1)];
                float p1 = simrow[1 * NMIN + ((i1 < NMIN) ? i1 : NMIN - 1)];
                float p2 = simrow[2 * NMIN + ((i2 < NMIN) ? i2 : NMIN - 1)];
                float p = p0 * p1 * p2;
                if ((i0 != pl0) | (i1 != pl1) | (i2 != pl2)) {
                    sum += -__logf(1.0f - p + EPSF);
                    cnt += 1.0f;
                }
            }
        }
        sum = warp_sum32(sum);
        cnt = warp_sum32(cnt);
        if (lane == 0) { s_red[warp][0] = sum; s_red[warp][1] = cnt; }
    }
    __syncthreads();

    if (tid < BT) {
        int s = tid;
        float sum = 0.f, cnt = 0.f;
#pragma unroll
        for (int w = 0; w < 8; w++) { sum += s_red[s * 8 + w][0]; cnt += s_red[s * 8 + w][1]; }
        float pprod = s_psim[s * H + 0] * s_psim[s * H + 1] * s_psim[s * H + 2];
        s_tot[s] = -__logf(pprod + EPSF) + sum / (cnt + EPSF);
    }
    __syncthreads();
    if (tid == 0)
        g_partial[blockIdx.x] = s_tot[0] + s_tot[1];

    // ================= Final: last block reduces 128 partials =================
    if (tid == 0) {
        __threadfence();
        s_amLast = (atomicAdd(&g_ticket, 1u) == NBLK - 1);
    }
    __syncthreads();
    if (s_amLast && warp == 0) {
        volatile float* gp = g_partial;
        float v = gp[lane] + gp[lane + 32] + gp[lane + 64] + gp[lane + 96];
        v = warp_sum32(v);
        if (lane == 0) {
            out[0] = v * (1.0f / (2.0f * (float)B));
            g_ticket = 0;
        }
    }
}

extern "C" void kernel_launch(void* const* d_in, const int* in_sizes, int n_in,
                              void* d_out, int out_size)
{
    const float* se   = (const float*)d_in[0];
    const float* c0   = (const float*)d_in[1];
    const float* c1   = (const float*)d_in[2];
    const float* c2   = (const float*)d_in[3];
    const int*   i2c0 = (const int*)d_in[4];
    const int*   i2c1 = (const int*)d_in[5];
    const int*   i2c2 = (const int*)d_in[6];
    const int*   idx  = (const int*)d_in[7];
    const int*   neg  = (const int*)d_in[8];
    float*       out  = (float*)d_out;

    hirl_fused<<<NBLK, NTHR>>>(se, c0, c1, c2, i2c0, i2c1, i2c2, idx, neg, out);
}